// round 1
// baseline (speedup 1.0000x reference)
#include <cuda_runtime.h>

#define NB  8
#define NC  512
#define NSP 1024          // H*W
#define NG  32
#define CPG 16            // channels per group
#define NH  8
#define HD  64
#define GN_EPS 1e-5f

// ---- scratch (static device globals: allocation-free kernel_launch) ----
__device__ float g_xn [NB * NC * NSP];        // 16 MB  group-normed x, [b][c][n]
__device__ float g_qkv[NB * 3 * NC * NSP];    // 48 MB  qkv,           [b][o][n]
__device__ float g_att[NB * NC * NSP];        // 16 MB  attn out,      [b][c][n]

// ============================================================================
// GroupNorm: one block per (batch, group). 16 channels x 1024 spatial each.
// ============================================================================
__global__ __launch_bounds__(256) void gn_kernel(const float* __restrict__ x,
                                                 const float* __restrict__ w,
                                                 const float* __restrict__ bta) {
    int blk = blockIdx.x;
    int batch = blk >> 5;
    int g = blk & 31;
    const float4* xp = (const float4*)(x + ((size_t)batch * NC + g * CPG) * NSP);
    float4* op = (float4*)(g_xn + ((size_t)batch * NC + g * CPG) * NSP);
    const int n4 = CPG * NSP / 4;   // 4096 float4
    float s = 0.f, ss = 0.f;
    for (int i = threadIdx.x; i < n4; i += 256) {
        float4 v = xp[i];
        s  += v.x + v.y + v.z + v.w;
        ss += v.x * v.x + v.y * v.y + v.z * v.z + v.w * v.w;
    }
    #pragma unroll
    for (int o = 16; o; o >>= 1) {
        s  += __shfl_xor_sync(0xffffffffu, s, o);
        ss += __shfl_xor_sync(0xffffffffu, ss, o);
    }
    __shared__ float sm0[8], sm1[8];
    __shared__ float mean_s, rstd_s;
    int warp = threadIdx.x >> 5, lane = threadIdx.x & 31;
    if (!lane) { sm0[warp] = s; sm1[warp] = ss; }
    __syncthreads();
    if (threadIdx.x == 0) {
        float ts = 0.f, tss = 0.f;
        #pragma unroll
        for (int i = 0; i < 8; i++) { ts += sm0[i]; tss += sm1[i]; }
        float inv_n = 1.0f / (CPG * NSP);
        float mean = ts * inv_n;
        float var = tss * inv_n - mean * mean;
        mean_s = mean;
        rstd_s = rsqrtf(var + GN_EPS);
    }
    __syncthreads();
    float mean = mean_s, rstd = rstd_s;
    for (int i = threadIdx.x; i < n4; i += 256) {
        int ch = g * CPG + (i >> 8);          // 256 float4 per channel
        float sc = w[ch] * rstd;
        float sh = bta[ch] - mean * sc;
        float4 v = xp[i];
        v.x = v.x * sc + sh; v.y = v.y * sc + sh;
        v.z = v.z * sc + sh; v.w = v.w * sc + sh;
        op[i] = v;
    }
}

// ============================================================================
// SGEMM 128x128x16 tile, 8x8 microtile, 256 threads.
//   out[b][m][n] = sum_c W[m][c] * X[b][c][n]   (X = g_xn or g_att)
// ============================================================================
__global__ __launch_bounds__(256) void qkv_gemm(const float* __restrict__ W,
                                                const float* __restrict__ bias) {
    int batch = blockIdx.z;
    const float* Xp = g_xn + (size_t)batch * NC * NSP;
    __shared__ float As[16][128];
    __shared__ float Bs[16][128];
    int tid = threadIdx.x;
    int tx = tid & 15, ty = tid >> 4;
    int m0 = blockIdx.y * 128, n0 = blockIdx.x * 128;
    float acc[8][8];
    #pragma unroll
    for (int i = 0; i < 8; i++)
        #pragma unroll
        for (int j = 0; j < 8; j++) acc[i][j] = 0.f;

    for (int k0 = 0; k0 < NC; k0 += 16) {
        #pragma unroll
        for (int t = 0; t < 2; t++) {
            int idx = tid + t * 256;
            int row = idx >> 2;
            int c4  = (idx & 3) << 2;
            float4 a = *(const float4*)&W[(size_t)(m0 + row) * NC + k0 + c4];
            As[c4 + 0][row] = a.x; As[c4 + 1][row] = a.y;
            As[c4 + 2][row] = a.z; As[c4 + 3][row] = a.w;
            int br_ = idx >> 5;
            int bc  = (idx & 31) << 2;
            *(float4*)&Bs[br_][bc] =
                *(const float4*)&Xp[(size_t)(k0 + br_) * NSP + n0 + bc];
        }
        __syncthreads();
        #pragma unroll
        for (int kk = 0; kk < 16; kk++) {
            float4 a0 = *(const float4*)&As[kk][ty * 8];
            float4 a1 = *(const float4*)&As[kk][ty * 8 + 4];
            float4 b0 = *(const float4*)&Bs[kk][tx * 8];
            float4 b1 = *(const float4*)&Bs[kk][tx * 8 + 4];
            float ar[8] = {a0.x, a0.y, a0.z, a0.w, a1.x, a1.y, a1.z, a1.w};
            float br2[8] = {b0.x, b0.y, b0.z, b0.w, b1.x, b1.y, b1.z, b1.w};
            #pragma unroll
            for (int i = 0; i < 8; i++)
                #pragma unroll
                for (int j = 0; j < 8; j++) acc[i][j] += ar[i] * br2[j];
        }
        __syncthreads();
    }
    #pragma unroll
    for (int i = 0; i < 8; i++) {
        int m = m0 + ty * 8 + i;
        float bi = bias[m];
        float* dst = g_qkv + ((size_t)batch * 3 * NC + m) * NSP + n0 + tx * 8;
        float4 o0 = {acc[i][0] + bi, acc[i][1] + bi, acc[i][2] + bi, acc[i][3] + bi};
        float4 o1 = {acc[i][4] + bi, acc[i][5] + bi, acc[i][6] + bi, acc[i][7] + bi};
        *(float4*)dst = o0;
        *(float4*)(dst + 4) = o1;
    }
}

__global__ __launch_bounds__(256) void proj_gemm(const float* __restrict__ W,
                                                 const float* __restrict__ bias,
                                                 const float* __restrict__ resid,
                                                 float* __restrict__ out) {
    int batch = blockIdx.z;
    const float* Xp = g_att + (size_t)batch * NC * NSP;
    __shared__ float As[16][128];
    __shared__ float Bs[16][128];
    int tid = threadIdx.x;
    int tx = tid & 15, ty = tid >> 4;
    int m0 = blockIdx.y * 128, n0 = blockIdx.x * 128;
    float acc[8][8];
    #pragma unroll
    for (int i = 0; i < 8; i++)
        #pragma unroll
        for (int j = 0; j < 8; j++) acc[i][j] = 0.f;

    for (int k0 = 0; k0 < NC; k0 += 16) {
        #pragma unroll
        for (int t = 0; t < 2; t++) {
            int idx = tid + t * 256;
            int row = idx >> 2;
            int c4  = (idx & 3) << 2;
            float4 a = *(const float4*)&W[(size_t)(m0 + row) * NC + k0 + c4];
            As[c4 + 0][row] = a.x; As[c4 + 1][row] = a.y;
            As[c4 + 2][row] = a.z; As[c4 + 3][row] = a.w;
            int br_ = idx >> 5;
            int bc  = (idx & 31) << 2;
            *(float4*)&Bs[br_][bc] =
                *(const float4*)&Xp[(size_t)(k0 + br_) * NSP + n0 + bc];
        }
        __syncthreads();
        #pragma unroll
        for (int kk = 0; kk < 16; kk++) {
            float4 a0 = *(const float4*)&As[kk][ty * 8];
            float4 a1 = *(const float4*)&As[kk][ty * 8 + 4];
            float4 b0 = *(const float4*)&Bs[kk][tx * 8];
            float4 b1 = *(const float4*)&Bs[kk][tx * 8 + 4];
            float ar[8] = {a0.x, a0.y, a0.z, a0.w, a1.x, a1.y, a1.z, a1.w};
            float br2[8] = {b0.x, b0.y, b0.z, b0.w, b1.x, b1.y, b1.z, b1.w};
            #pragma unroll
            for (int i = 0; i < 8; i++)
                #pragma unroll
                for (int j = 0; j < 8; j++) acc[i][j] += ar[i] * br2[j];
        }
        __syncthreads();
    }
    #pragma unroll
    for (int i = 0; i < 8; i++) {
        int m = m0 + ty * 8 + i;
        float bi = bias[m];
        size_t base = ((size_t)batch * NC + m) * NSP + n0 + tx * 8;
        float4 r0 = *(const float4*)&resid[base];
        float4 r1 = *(const float4*)&resid[base + 4];
        float4 o0 = {acc[i][0] + bi + r0.x, acc[i][1] + bi + r0.y,
                     acc[i][2] + bi + r0.z, acc[i][3] + bi + r0.w};
        float4 o1 = {acc[i][4] + bi + r1.x, acc[i][5] + bi + r1.y,
                     acc[i][6] + bi + r1.z, acc[i][7] + bi + r1.w};
        *(float4*)&out[base] = o0;
        *(float4*)&out[base + 4] = o1;
    }
}

// ============================================================================
// Flash-style attention: block = (q-tile of 64, head, batch). N=1024, hd=64.
// smem tiles stored [d][n] (Q,K) / transposed V [k][d] / P [q][k].
// ============================================================================
#define PPAD 68   // float4-aligned padded row (68*4 bytes divisible by 16)
#define ATTN_SMEM ((64*64 + 64*64 + 64*PPAD + 64*PPAD) * 4)

__global__ __launch_bounds__(256) void attn_kernel() {
    extern __shared__ float smem[];
    float* Qs = smem;                 // [64][64]   Qs[d][q]
    float* Ks = Qs + 64 * 64;         // [64][64]   Ks[d][k]
    float* Vt = Ks + 64 * 64;         // [64][PPAD] Vt[k][d]
    float* Ps = Vt + 64 * PPAD;       // [64][PPAD] Ps[q][k]

    int qt = blockIdx.x, h = blockIdx.y, batch = blockIdx.z;
    const float* qp = g_qkv + ((size_t)batch * 3 * NC + 0 * NC + h * HD) * NSP;
    const float* kp = g_qkv + ((size_t)batch * 3 * NC + 1 * NC + h * HD) * NSP;
    const float* vp = g_qkv + ((size_t)batch * 3 * NC + 2 * NC + h * HD) * NSP;
    int q0 = qt * 64;
    int tid = threadIdx.x, tx = tid & 15, ty = tid >> 4;

    // load Q tile (coalesced)
    #pragma unroll
    for (int t = 0; t < 4; t++) {
        int idx = tid + t * 256;       // 1024 float4
        int d = idx >> 4;
        int j4 = (idx & 15) << 2;
        *(float4*)&Qs[d * 64 + j4] = *(const float4*)&qp[(size_t)d * NSP + q0 + j4];
    }

    float m[4], l[4], o[4][4];
    #pragma unroll
    for (int i = 0; i < 4; i++) {
        m[i] = -1e30f; l[i] = 0.f;
        #pragma unroll
        for (int j = 0; j < 4; j++) o[i][j] = 0.f;
    }

    for (int kt = 0; kt < 16; kt++) {
        int k0 = kt * 64;
        __syncthreads();   // prev-iter readers of Ks/Vt done (also covers Qs on kt=0)
        #pragma unroll
        for (int t = 0; t < 4; t++) {
            int idx = tid + t * 256;
            int d = idx >> 4;
            int j4 = (idx & 15) << 2;
            *(float4*)&Ks[d * 64 + j4] = *(const float4*)&kp[(size_t)d * NSP + k0 + j4];
            float4 v = *(const float4*)&vp[(size_t)d * NSP + k0 + j4];
            Vt[(j4 + 0) * PPAD + d] = v.x;
            Vt[(j4 + 1) * PPAD + d] = v.y;
            Vt[(j4 + 2) * PPAD + d] = v.z;
            Vt[(j4 + 3) * PPAD + d] = v.w;
        }
        __syncthreads();

        // S = (Q^T K) * scale  -> 4x4 per thread
        float s[4][4];
        #pragma unroll
        for (int i = 0; i < 4; i++)
            #pragma unroll
            for (int j = 0; j < 4; j++) s[i][j] = 0.f;
        #pragma unroll 8
        for (int dd = 0; dd < 64; dd++) {
            float4 a = *(const float4*)&Qs[dd * 64 + ty * 4];
            float4 b = *(const float4*)&Ks[dd * 64 + tx * 4];
            float ar[4] = {a.x, a.y, a.z, a.w};
            float br[4] = {b.x, b.y, b.z, b.w};
            #pragma unroll
            for (int i = 0; i < 4; i++)
                #pragma unroll
                for (int j = 0; j < 4; j++) s[i][j] += ar[i] * br[j];
        }

        // online softmax, write P to smem
        #pragma unroll
        for (int i = 0; i < 4; i++) {
            #pragma unroll
            for (int j = 0; j < 4; j++) s[i][j] *= 0.125f;   // hd^-0.5
            float mx = fmaxf(fmaxf(s[i][0], s[i][1]), fmaxf(s[i][2], s[i][3]));
            #pragma unroll
            for (int off = 8; off; off >>= 1)
                mx = fmaxf(mx, __shfl_xor_sync(0xffffffffu, mx, off, 16));
            float mnew = fmaxf(m[i], mx);
            float corr = __expf(m[i] - mnew);
            float rs = 0.f;
            #pragma unroll
            for (int j = 0; j < 4; j++) {
                float p = __expf(s[i][j] - mnew);
                Ps[(ty * 4 + i) * PPAD + tx * 4 + j] = p;
                rs += p;
            }
            #pragma unroll
            for (int off = 8; off; off >>= 1)
                rs += __shfl_xor_sync(0xffffffffu, rs, off, 16);
            l[i] = l[i] * corr + rs;
            m[i] = mnew;
            #pragma unroll
            for (int j = 0; j < 4; j++) o[i][j] *= corr;
        }
        __syncthreads();

        // O += P @ V : thread owns rows q = ty*4+i, cols d = tx*4+j
        #pragma unroll 4
        for (int kk = 0; kk < 64; kk += 4) {
            float pr[4][4];
            #pragma unroll
            for (int i = 0; i < 4; i++) {
                float4 p = *(const float4*)&Ps[(ty * 4 + i) * PPAD + kk];
                pr[i][0] = p.x; pr[i][1] = p.y; pr[i][2] = p.z; pr[i][3] = p.w;
            }
            #pragma unroll
            for (int u = 0; u < 4; u++) {
                float4 b = *(const float4*)&Vt[(kk + u) * PPAD + tx * 4];
                float br[4] = {b.x, b.y, b.z, b.w};
                #pragma unroll
                for (int i = 0; i < 4; i++)
                    #pragma unroll
                    for (int j = 0; j < 4; j++) o[i][j] += pr[i][u] * br[j];
            }
        }
    }

    // finalize: divide by l, transpose through smem, coalesced store as [d][q]
    __syncthreads();
    #pragma unroll
    for (int i = 0; i < 4; i++) {
        float inv = 1.0f / l[i];
        #pragma unroll
        for (int j = 0; j < 4; j++)
            Ps[(tx * 4 + j) * PPAD + ty * 4 + i] = o[i][j] * inv;  // Ps[d][q]
    }
    __syncthreads();
    float* op = g_att + ((size_t)batch * NC + h * HD) * NSP;
    #pragma unroll
    for (int t = 0; t < 4; t++) {
        int idx = tid + t * 256;
        int d = idx >> 4;
        int j4 = (idx & 15) << 2;
        *(float4*)&op[(size_t)d * NSP + q0 + j4] = *(const float4*)&Ps[d * PPAD + j4];
    }
}

// ============================================================================
extern "C" void kernel_launch(void* const* d_in, const int* in_sizes, int n_in,
                              void* d_out, int out_size) {
    const float* x      = (const float*)d_in[0];
    const float* gn_w   = (const float*)d_in[1];
    const float* gn_b   = (const float*)d_in[2];
    const float* qkv_w  = (const float*)d_in[3];
    const float* qkv_b  = (const float*)d_in[4];
    const float* proj_w = (const float*)d_in[5];
    const float* proj_b = (const float*)d_in[6];
    float* out = (float*)d_out;

    gn_kernel<<<NB * NG, 256>>>(x, gn_w, gn_b);
    qkv_gemm<<<dim3(NSP / 128, 3 * NC / 128, NB), 256>>>(qkv_w, qkv_b);
    cudaFuncSetAttribute(attn_kernel, cudaFuncAttributeMaxDynamicSharedMemorySize,
                         ATTN_SMEM);
    attn_kernel<<<dim3(NSP / 64, NH, NB), 256, ATTN_SMEM>>>();
    proj_gemm<<<dim3(NSP / 128, NC / 128, NB), 256>>>(proj_w, proj_b, x, out);
}

// round 4
// speedup vs baseline: 1.4112x; 1.4112x over previous
#include <cuda_runtime.h>
#include <cstdint>

#define NB  8
#define NC  512
#define NSP 1024          // H*W
#define NG  32
#define CPG 16            // channels per group
#define NH  8
#define HD  64
#define GN_EPS 1e-5f

// single dynamic-smem symbol for the whole TU (attention only)
extern __shared__ __align__(16) char dsmem[];

// ---- scratch (static device globals: allocation-free kernel_launch) ----
__device__ float g_xn [NB * NC * NSP];        // group-normed x, [b][c][n]
__device__ float g_qkv[NB * 3 * NC * NSP];    // qkv,            [b][o][n]
__device__ float g_att[NB * NC * NSP];        // attn out,       [b][c][n]

__device__ __forceinline__ uint32_t f2tf32(float x) {
    uint32_t r;
    asm("cvt.rna.tf32.f32 %0, %1;" : "=r"(r) : "f"(x));
    return r;
}

// ============================================================================
// GroupNorm: one block per (batch, group). 16 channels x 1024 spatial each.
// ============================================================================
__global__ __launch_bounds__(256) void gn_kernel(const float* __restrict__ x,
                                                 const float* __restrict__ w,
                                                 const float* __restrict__ bta) {
    int blk = blockIdx.x;
    int batch = blk >> 5;
    int g = blk & 31;
    const float4* xp = (const float4*)(x + ((size_t)batch * NC + g * CPG) * NSP);
    float4* op = (float4*)(g_xn + ((size_t)batch * NC + g * CPG) * NSP);
    const int n4 = CPG * NSP / 4;   // 4096 float4
    float s = 0.f, ss = 0.f;
    for (int i = threadIdx.x; i < n4; i += 256) {
        float4 v = xp[i];
        s  += v.x + v.y + v.z + v.w;
        ss += v.x * v.x + v.y * v.y + v.z * v.z + v.w * v.w;
    }
    #pragma unroll
    for (int o = 16; o; o >>= 1) {
        s  += __shfl_xor_sync(0xffffffffu, s, o);
        ss += __shfl_xor_sync(0xffffffffu, ss, o);
    }
    __shared__ float sm0[8], sm1[8];
    __shared__ float mean_s, rstd_s;
    int warp = threadIdx.x >> 5, lane = threadIdx.x & 31;
    if (!lane) { sm0[warp] = s; sm1[warp] = ss; }
    __syncthreads();
    if (threadIdx.x == 0) {
        float ts = 0.f, tss = 0.f;
        #pragma unroll
        for (int i = 0; i < 8; i++) { ts += sm0[i]; tss += sm1[i]; }
        float inv_n = 1.0f / (CPG * NSP);
        float mean = ts * inv_n;
        float var = tss * inv_n - mean * mean;
        mean_s = mean;
        rstd_s = rsqrtf(var + GN_EPS);
    }
    __syncthreads();
    float mean = mean_s, rstd = rstd_s;
    for (int i = threadIdx.x; i < n4; i += 256) {
        int ch = g * CPG + (i >> 8);
        float sc = w[ch] * rstd;
        float sh = bta[ch] - mean * sc;
        float4 v = xp[i];
        v.x = v.x * sc + sh; v.y = v.y * sc + sh;
        v.z = v.z * sc + sh; v.w = v.w * sc + sh;
        op[i] = v;
    }
}

// ============================================================================
// tf32 mma.sync GEMM: out[b][m][n] = sum_k A[m][k] * B[b][k][n] (+bias,+resid)
// A: [Mtot][512] row-major (weights). B: [b][512][1024] ([c][n]).
// CTA tile 128x128, 8 warps 4x2 (warp tile 32x64), K staged by 32.
// ============================================================================
#define ASTR 36
#define BSTR 132

__global__ __launch_bounds__(256, 2) void gemm_mma(const float* __restrict__ A,
                                                   const float* __restrict__ Bm,
                                                   const float* __restrict__ bias,
                                                   const float* __restrict__ resid,
                                                   float* __restrict__ out) {
    __shared__ uint32_t As[128 * ASTR];   // [m][k] tf32 bits
    __shared__ uint32_t Bs[32 * BSTR];    // [k][n] tf32 bits

    const int tid = threadIdx.x;
    const int wid = tid >> 5, lid = tid & 31;
    const int g = lid >> 2, tig = lid & 3;
    const int wm = (wid >> 1) * 32, wn = (wid & 1) * 64;
    const int m0 = blockIdx.y * 128, n0 = blockIdx.x * 128;
    const int batch = blockIdx.z;
    const float* Bp = Bm + (size_t)batch * NC * NSP;

    float acc[2][8][4];
    #pragma unroll
    for (int mt = 0; mt < 2; mt++)
        #pragma unroll
        for (int nt = 0; nt < 8; nt++)
            #pragma unroll
            for (int r = 0; r < 4; r++) acc[mt][nt][r] = 0.f;

    for (int ks = 0; ks < NC / 32; ks++) {
        int k0 = ks * 32;
        #pragma unroll
        for (int it = 0; it < 4; it++) {
            int idx = tid + it * 256;
            // A: 128 rows x 32 cols
            int r = idx >> 3, c4 = (idx & 7) << 2;
            float4 va = *(const float4*)&A[(size_t)(m0 + r) * NC + k0 + c4];
            uint4 ua = {f2tf32(va.x), f2tf32(va.y), f2tf32(va.z), f2tf32(va.w)};
            *(uint4*)&As[r * ASTR + c4] = ua;
            // B: 32 rows x 128 cols
            int kr = idx >> 5, nq = (idx & 31) << 2;
            float4 vb = *(const float4*)&Bp[(size_t)(k0 + kr) * NSP + n0 + nq];
            uint4 ub = {f2tf32(vb.x), f2tf32(vb.y), f2tf32(vb.z), f2tf32(vb.w)};
            *(uint4*)&Bs[kr * BSTR + nq] = ub;
        }
        __syncthreads();

        #pragma unroll
        for (int kk = 0; kk < 4; kk++) {
            uint32_t af[2][4];
            #pragma unroll
            for (int mt = 0; mt < 2; mt++) {
                int r0 = wm + mt * 16 + g;
                af[mt][0] = As[(r0    ) * ASTR + kk * 8 + tig];
                af[mt][1] = As[(r0 + 8) * ASTR + kk * 8 + tig];
                af[mt][2] = As[(r0    ) * ASTR + kk * 8 + tig + 4];
                af[mt][3] = As[(r0 + 8) * ASTR + kk * 8 + tig + 4];
            }
            uint32_t bf[8][2];
            #pragma unroll
            for (int nt = 0; nt < 8; nt++) {
                int c = wn + nt * 8 + g;
                bf[nt][0] = Bs[(kk * 8 + tig    ) * BSTR + c];
                bf[nt][1] = Bs[(kk * 8 + tig + 4) * BSTR + c];
            }
            #pragma unroll
            for (int mt = 0; mt < 2; mt++)
                #pragma unroll
                for (int nt = 0; nt < 8; nt++) {
                    asm volatile(
                        "mma.sync.aligned.m16n8k8.row.col.f32.tf32.tf32.f32 "
                        "{%0,%1,%2,%3}, {%4,%5,%6,%7}, {%8,%9}, {%0,%1,%2,%3};"
                        : "+f"(acc[mt][nt][0]), "+f"(acc[mt][nt][1]),
                          "+f"(acc[mt][nt][2]), "+f"(acc[mt][nt][3])
                        : "r"(af[mt][0]), "r"(af[mt][1]),
                          "r"(af[mt][2]), "r"(af[mt][3]),
                          "r"(bf[nt][0]), "r"(bf[nt][1]));
                }
        }
        __syncthreads();
    }

    // epilogue
    size_t bstride = (size_t)gridDim.y * 128 * NSP;
    #pragma unroll
    for (int mt = 0; mt < 2; mt++) {
        int row0 = m0 + wm + mt * 16 + g;
        float b0v = bias[row0], b1v = bias[row0 + 8];
        #pragma unroll
        for (int nt = 0; nt < 8; nt++) {
            int col = n0 + wn + nt * 8 + 2 * tig;
            size_t o0 = (size_t)batch * bstride + (size_t)row0 * NSP + col;
            size_t o1 = o0 + 8 * NSP;
            float2 v0 = {acc[mt][nt][0] + b0v, acc[mt][nt][1] + b0v};
            float2 v1 = {acc[mt][nt][2] + b1v, acc[mt][nt][3] + b1v};
            if (resid) {
                float2 r0 = *(const float2*)&resid[o0];
                float2 r1 = *(const float2*)&resid[o1];
                v0.x += r0.x; v0.y += r0.y;
                v1.x += r1.x; v1.y += r1.y;
            }
            *(float2*)&out[o0] = v0;
            *(float2*)&out[o1] = v1;
        }
    }
}

// ============================================================================
// Flash-style attention: block = (q-tile of 64, head, batch). N=1024, hd=64.
// reads g_qkv [b][o][n]; writes g_att [b][c][n]
// ============================================================================
#define PPAD 68
#define ATTN_SMEM ((64*64 + 64*64 + 64*PPAD + 64*PPAD) * 4)

__global__ __launch_bounds__(256) void attn_kernel() {
    float* smem = (float*)dsmem;
    float* Qs = smem;                 // [64][64]   Qs[d][q]
    float* Ks = Qs + 64 * 64;         // [64][64]   Ks[d][k]
    float* Vt = Ks + 64 * 64;         // [64][PPAD] Vt[k][d]
    float* Ps = Vt + 64 * PPAD;       // [64][PPAD] Ps[q][k]

    int qt = blockIdx.x, h = blockIdx.y, batch = blockIdx.z;
    const float* qp = g_qkv + ((size_t)batch * 3 * NC + 0 * NC + h * HD) * NSP;
    const float* kp = g_qkv + ((size_t)batch * 3 * NC + 1 * NC + h * HD) * NSP;
    const float* vp = g_qkv + ((size_t)batch * 3 * NC + 2 * NC + h * HD) * NSP;
    int q0 = qt * 64;
    int tid = threadIdx.x, tx = tid & 15, ty = tid >> 4;

    #pragma unroll
    for (int t = 0; t < 4; t++) {
        int idx = tid + t * 256;
        int d = idx >> 4;
        int j4 = (idx & 15) << 2;
        *(float4*)&Qs[d * 64 + j4] = *(const float4*)&qp[(size_t)d * NSP + q0 + j4];
    }

    float m[4], l[4], o[4][4];
    #pragma unroll
    for (int i = 0; i < 4; i++) {
        m[i] = -1e30f; l[i] = 0.f;
        #pragma unroll
        for (int j = 0; j < 4; j++) o[i][j] = 0.f;
    }

    for (int kt = 0; kt < 16; kt++) {
        int k0 = kt * 64;
        __syncthreads();
        #pragma unroll
        for (int t = 0; t < 4; t++) {
            int idx = tid + t * 256;
            int d = idx >> 4;
            int j4 = (idx & 15) << 2;
            *(float4*)&Ks[d * 64 + j4] = *(const float4*)&kp[(size_t)d * NSP + k0 + j4];
            float4 v = *(const float4*)&vp[(size_t)d * NSP + k0 + j4];
            Vt[(j4 + 0) * PPAD + d] = v.x;
            Vt[(j4 + 1) * PPAD + d] = v.y;
            Vt[(j4 + 2) * PPAD + d] = v.z;
            Vt[(j4 + 3) * PPAD + d] = v.w;
        }
        __syncthreads();

        float s[4][4];
        #pragma unroll
        for (int i = 0; i < 4; i++)
            #pragma unroll
            for (int j = 0; j < 4; j++) s[i][j] = 0.f;
        #pragma unroll 8
        for (int dd = 0; dd < 64; dd++) {
            float4 a = *(const float4*)&Qs[dd * 64 + ty * 4];
            float4 b = *(const float4*)&Ks[dd * 64 + tx * 4];
            float ar[4] = {a.x, a.y, a.z, a.w};
            float br[4] = {b.x, b.y, b.z, b.w};
            #pragma unroll
            for (int i = 0; i < 4; i++)
                #pragma unroll
                for (int j = 0; j < 4; j++) s[i][j] += ar[i] * br[j];
        }

        #pragma unroll
        for (int i = 0; i < 4; i++) {
            #pragma unroll
            for (int j = 0; j < 4; j++) s[i][j] *= 0.125f;
            float mx = fmaxf(fmaxf(s[i][0], s[i][1]), fmaxf(s[i][2], s[i][3]));
            #pragma unroll
            for (int off = 8; off; off >>= 1)
                mx = fmaxf(mx, __shfl_xor_sync(0xffffffffu, mx, off, 16));
            float mnew = fmaxf(m[i], mx);
            float corr = __expf(m[i] - mnew);
            float rs = 0.f;
            #pragma unroll
            for (int j = 0; j < 4; j++) {
                float p = __expf(s[i][j] - mnew);
                Ps[(ty * 4 + i) * PPAD + tx * 4 + j] = p;
                rs += p;
            }
            #pragma unroll
            for (int off = 8; off; off >>= 1)
                rs += __shfl_xor_sync(0xffffffffu, rs, off, 16);
            l[i] = l[i] * corr + rs;
            m[i] = mnew;
            #pragma unroll
            for (int j = 0; j < 4; j++) o[i][j] *= corr;
        }
        __syncthreads();

        #pragma unroll 4
        for (int kk = 0; kk < 64; kk += 4) {
            float pr[4][4];
            #pragma unroll
            for (int i = 0; i < 4; i++) {
                float4 p = *(const float4*)&Ps[(ty * 4 + i) * PPAD + kk];
                pr[i][0] = p.x; pr[i][1] = p.y; pr[i][2] = p.z; pr[i][3] = p.w;
            }
            #pragma unroll
            for (int u = 0; u < 4; u++) {
                float4 b = *(const float4*)&Vt[(kk + u) * PPAD + tx * 4];
                float br[4] = {b.x, b.y, b.z, b.w};
                #pragma unroll
                for (int i = 0; i < 4; i++)
                    #pragma unroll
                    for (int j = 0; j < 4; j++) o[i][j] += pr[i][u] * br[j];
            }
        }
    }

    // finalize: divide by l, transpose through smem, coalesced store as [d][q]
    __syncthreads();
    #pragma unroll
    for (int i = 0; i < 4; i++) {
        float inv = 1.0f / l[i];
        #pragma unroll
        for (int j = 0; j < 4; j++)
            Ps[(tx * 4 + j) * PPAD + ty * 4 + i] = o[i][j] * inv;  // Ps[d][q]
    }
    __syncthreads();
    float* op = g_att + ((size_t)batch * NC + h * HD) * NSP;
    #pragma unroll
    for (int t = 0; t < 4; t++) {
        int idx = tid + t * 256;
        int d = idx >> 4;
        int j4 = (idx & 15) << 2;
        *(float4*)&op[(size_t)d * NSP + q0 + j4] = *(const float4*)&Ps[d * PPAD + j4];
    }
}

// ============================================================================
extern "C" void kernel_launch(void* const* d_in, const int* in_sizes, int n_in,
                              void* d_out, int out_size) {
    const float* x      = (const float*)d_in[0];
    const float* gn_w   = (const float*)d_in[1];
    const float* gn_b   = (const float*)d_in[2];
    const float* qkv_w  = (const float*)d_in[3];
    const float* qkv_b  = (const float*)d_in[4];
    const float* proj_w = (const float*)d_in[5];
    const float* proj_b = (const float*)d_in[6];
    float* out = (float*)d_out;

    float *p_xn, *p_att, *p_qkv;
    cudaGetSymbolAddress((void**)&p_xn, g_xn);
    cudaGetSymbolAddress((void**)&p_att, g_att);
    cudaGetSymbolAddress((void**)&p_qkv, g_qkv);

    cudaFuncSetAttribute(attn_kernel, cudaFuncAttributeMaxDynamicSharedMemorySize,
                         ATTN_SMEM);

    gn_kernel<<<NB * NG, 256>>>(x, gn_w, gn_b);
    // QKV: A=qkv_w [1536][512], B=g_xn [b][512][1024], out=g_qkv [b][1536][1024]
    gemm_mma<<<dim3(8, 12, NB), 256>>>(qkv_w, p_xn, qkv_b, nullptr, p_qkv);
    attn_kernel<<<dim3(NSP / 64, NH, NB), 256, ATTN_SMEM>>>();
    // proj: A=proj_w [512][512], B=g_att, out=d_out (+bias +residual)
    gemm_mma<<<dim3(8, 4, NB), 256>>>(proj_w, p_att, proj_b, x, out);
}

// round 5
// speedup vs baseline: 2.4709x; 1.7509x over previous
#include <cuda_runtime.h>
#include <cstdint>

#define NB  8
#define NC  512
#define NSP 1024          // H*W
#define NG  32
#define CPG 16            // channels per group
#define NH  8
#define HD  64
#define GN_EPS 1e-5f

// single dynamic-smem symbol for the whole TU (attention only)
extern __shared__ __align__(16) char dsmem[];

// ---- scratch (static device globals: allocation-free kernel_launch) ----
__device__ float g_xn [NB * NC * NSP];        // group-normed x, [b][c][n]
__device__ float g_qkv[NB * 3 * NC * NSP];    // qkv,            [b][o][n]
__device__ float g_att[NB * NC * NSP];        // attn out,       [b][c][n]

__device__ __forceinline__ uint32_t f2tf32(float x) {
    uint32_t r;
    asm("cvt.rna.tf32.f32 %0, %1;" : "=r"(r) : "f"(x));
    return r;
}
__device__ __forceinline__ uint4 cvt4(float4 v) {
    uint4 u = {f2tf32(v.x), f2tf32(v.y), f2tf32(v.z), f2tf32(v.w)};
    return u;
}
#define MMA_TF32(acc, a0, a1, a2, a3, b0, b1)                                  \
    asm volatile(                                                              \
        "mma.sync.aligned.m16n8k8.row.col.f32.tf32.tf32.f32 "                  \
        "{%0,%1,%2,%3}, {%4,%5,%6,%7}, {%8,%9}, {%0,%1,%2,%3};"                \
        : "+f"(acc[0]), "+f"(acc[1]), "+f"(acc[2]), "+f"(acc[3])               \
        : "r"(a0), "r"(a1), "r"(a2), "r"(a3), "r"(b0), "r"(b1))

// ============================================================================
// GroupNorm: one block per (batch, group). 16 channels x 1024 spatial each.
// ============================================================================
__global__ __launch_bounds__(256) void gn_kernel(const float* __restrict__ x,
                                                 const float* __restrict__ w,
                                                 const float* __restrict__ bta) {
    int blk = blockIdx.x;
    int batch = blk >> 5;
    int g = blk & 31;
    const float4* xp = (const float4*)(x + ((size_t)batch * NC + g * CPG) * NSP);
    float4* op = (float4*)(g_xn + ((size_t)batch * NC + g * CPG) * NSP);
    const int n4 = CPG * NSP / 4;
    float s = 0.f, ss = 0.f;
    for (int i = threadIdx.x; i < n4; i += 256) {
        float4 v = xp[i];
        s  += v.x + v.y + v.z + v.w;
        ss += v.x * v.x + v.y * v.y + v.z * v.z + v.w * v.w;
    }
    #pragma unroll
    for (int o = 16; o; o >>= 1) {
        s  += __shfl_xor_sync(0xffffffffu, s, o);
        ss += __shfl_xor_sync(0xffffffffu, ss, o);
    }
    __shared__ float sm0[8], sm1[8];
    __shared__ float mean_s, rstd_s;
    int warp = threadIdx.x >> 5, lane = threadIdx.x & 31;
    if (!lane) { sm0[warp] = s; sm1[warp] = ss; }
    __syncthreads();
    if (threadIdx.x == 0) {
        float ts = 0.f, tss = 0.f;
        #pragma unroll
        for (int i = 0; i < 8; i++) { ts += sm0[i]; tss += sm1[i]; }
        float inv_n = 1.0f / (CPG * NSP);
        float mean = ts * inv_n;
        float var = tss * inv_n - mean * mean;
        mean_s = mean;
        rstd_s = rsqrtf(var + GN_EPS);
    }
    __syncthreads();
    float mean = mean_s, rstd = rstd_s;
    for (int i = threadIdx.x; i < n4; i += 256) {
        int ch = g * CPG + (i >> 8);
        float sc = w[ch] * rstd;
        float sh = bta[ch] - mean * sc;
        float4 v = xp[i];
        v.x = v.x * sc + sh; v.y = v.y * sc + sh;
        v.z = v.z * sc + sh; v.w = v.w * sc + sh;
        op[i] = v;
    }
}

// ============================================================================
// tf32 mma.sync GEMM: out[b][m][n] = sum_k A[m][k] * B[b][k][n] (+bias,+resid)
// ============================================================================
#define ASTR 36
#define BSTR 132

__global__ __launch_bounds__(256, 2) void gemm_mma(const float* __restrict__ A,
                                                   const float* __restrict__ Bm,
                                                   const float* __restrict__ bias,
                                                   const float* __restrict__ resid,
                                                   float* __restrict__ out) {
    __shared__ uint32_t As[128 * ASTR];   // [m][k] tf32 bits
    __shared__ uint32_t Bs[32 * BSTR];    // [k][n] tf32 bits

    const int tid = threadIdx.x;
    const int wid = tid >> 5, lid = tid & 31;
    const int g = lid >> 2, tig = lid & 3;
    const int wm = (wid >> 1) * 32, wn = (wid & 1) * 64;
    const int m0 = blockIdx.y * 128, n0 = blockIdx.x * 128;
    const int batch = blockIdx.z;
    const float* Bp = Bm + (size_t)batch * NC * NSP;

    float acc[2][8][4];
    #pragma unroll
    for (int mt = 0; mt < 2; mt++)
        #pragma unroll
        for (int nt = 0; nt < 8; nt++)
            #pragma unroll
            for (int r = 0; r < 4; r++) acc[mt][nt][r] = 0.f;

    for (int ks = 0; ks < NC / 32; ks++) {
        int k0 = ks * 32;
        #pragma unroll
        for (int it = 0; it < 4; it++) {
            int idx = tid + it * 256;
            int r = idx >> 3, c4 = (idx & 7) << 2;
            *(uint4*)&As[r * ASTR + c4] =
                cvt4(*(const float4*)&A[(size_t)(m0 + r) * NC + k0 + c4]);
            int kr = idx >> 5, nq = (idx & 31) << 2;
            *(uint4*)&Bs[kr * BSTR + nq] =
                cvt4(*(const float4*)&Bp[(size_t)(k0 + kr) * NSP + n0 + nq]);
        }
        __syncthreads();

        #pragma unroll
        for (int kk = 0; kk < 4; kk++) {
            uint32_t af[2][4];
            #pragma unroll
            for (int mt = 0; mt < 2; mt++) {
                int r0 = wm + mt * 16 + g;
                af[mt][0] = As[(r0    ) * ASTR + kk * 8 + tig];
                af[mt][1] = As[(r0 + 8) * ASTR + kk * 8 + tig];
                af[mt][2] = As[(r0    ) * ASTR + kk * 8 + tig + 4];
                af[mt][3] = As[(r0 + 8) * ASTR + kk * 8 + tig + 4];
            }
            uint32_t bf[8][2];
            #pragma unroll
            for (int nt = 0; nt < 8; nt++) {
                int c = wn + nt * 8 + g;
                bf[nt][0] = Bs[(kk * 8 + tig    ) * BSTR + c];
                bf[nt][1] = Bs[(kk * 8 + tig + 4) * BSTR + c];
            }
            #pragma unroll
            for (int mt = 0; mt < 2; mt++)
                #pragma unroll
                for (int nt = 0; nt < 8; nt++)
                    MMA_TF32(acc[mt][nt], af[mt][0], af[mt][1], af[mt][2],
                             af[mt][3], bf[nt][0], bf[nt][1]);
        }
        __syncthreads();
    }

    size_t bstride = (size_t)gridDim.y * 128 * NSP;
    #pragma unroll
    for (int mt = 0; mt < 2; mt++) {
        int row0 = m0 + wm + mt * 16 + g;
        float b0v = bias[row0], b1v = bias[row0 + 8];
        #pragma unroll
        for (int nt = 0; nt < 8; nt++) {
            int col = n0 + wn + nt * 8 + 2 * tig;
            size_t o0 = (size_t)batch * bstride + (size_t)row0 * NSP + col;
            size_t o1 = o0 + 8 * NSP;
            float2 v0 = {acc[mt][nt][0] + b0v, acc[mt][nt][1] + b0v};
            float2 v1 = {acc[mt][nt][2] + b1v, acc[mt][nt][3] + b1v};
            if (resid) {
                float2 r0 = *(const float2*)&resid[o0];
                float2 r1 = *(const float2*)&resid[o1];
                v0.x += r0.x; v0.y += r0.y;
                v1.x += r1.x; v1.y += r1.y;
            }
            *(float2*)&out[o0] = v0;
            *(float2*)&out[o1] = v1;
        }
    }
}

// ============================================================================
// Tensor-core flash attention. Block = (q-tile 128, head, batch).
// S[q][k] = Qs[d][q]^T Ks[d][k];  O^T[d][q] = Vs[d][k] * P^T[k][q].
// Warp w: S rows [w*16, w*16+16);  PV: d-tile (w&3)*16, q-half (w>>2)*64.
// ============================================================================
#define QT   128
#define QSTR 132
#define KSTR 68
#define PSTR 68
#define ATTN_SMEM ((64*QSTR + 64*KSTR + 64*KSTR + QT*PSTR + 256) * 4)

__global__ __launch_bounds__(256, 2) void attn_mma() {
    uint32_t* su = (uint32_t*)dsmem;
    uint32_t* Qs = su;                     // [64 d][QSTR]
    uint32_t* Ks = Qs + 64 * QSTR;         // [64 d][KSTR]
    uint32_t* Vs = Ks + 64 * KSTR;         // [64 d][KSTR]
    uint32_t* Ps = Vs + 64 * KSTR;         // [QT q][PSTR]
    float* corr = (float*)(Ps + QT * PSTR);
    float* linv = corr + 128;

    int qt = blockIdx.x, h = blockIdx.y, b = blockIdx.z;
    const float* qp = g_qkv + ((size_t)b * 3 * NC + h * HD) * NSP;
    const float* kp = qp + (size_t)NC * NSP;
    const float* vp = qp + (size_t)2 * NC * NSP;
    int q0 = qt * QT;
    int tid = threadIdx.x, wid = tid >> 5, lid = tid & 31;
    int g = lid >> 2, tig = lid & 3;
    int wq = wid * 16;                 // S row base
    int dt = (wid & 3) * 16;           // PV d-tile base
    int qh = (wid >> 2) * 64;          // PV q-half base

    // load Q tile: 64 d x 128 q
    #pragma unroll
    for (int it = 0; it < 8; it++) {
        int idx = tid + it * 256;            // 2048 float4
        int d = idx >> 5, q4 = (idx & 31) << 2;
        *(uint4*)&Qs[d * QSTR + q4] =
            cvt4(*(const float4*)&qp[(size_t)d * NSP + q0 + q4]);
    }

    float mrow[2] = {-1e30f, -1e30f};
    float lrow[2] = {0.f, 0.f};
    float acc_o[8][4];
    #pragma unroll
    for (int nt = 0; nt < 8; nt++)
        #pragma unroll
        for (int r = 0; r < 4; r++) acc_o[nt][r] = 0.f;

    for (int ktile = 0; ktile < 16; ktile++) {
        int k0 = ktile * 64;
        __syncthreads();
        // load K,V tiles: 64 d x 64 k each
        #pragma unroll
        for (int it = 0; it < 4; it++) {
            int idx = tid + it * 256;        // 1024 float4 per tile
            int d = idx >> 4, k4 = (idx & 15) << 2;
            *(uint4*)&Ks[d * KSTR + k4] =
                cvt4(*(const float4*)&kp[(size_t)d * NSP + k0 + k4]);
            *(uint4*)&Vs[d * KSTR + k4] =
                cvt4(*(const float4*)&vp[(size_t)d * NSP + k0 + k4]);
        }
        __syncthreads();

        // ---- S = Q^T K ----
        float acc_s[8][4];
        #pragma unroll
        for (int nt = 0; nt < 8; nt++)
            #pragma unroll
            for (int r = 0; r < 4; r++) acc_s[nt][r] = 0.f;
        #pragma unroll
        for (int kk = 0; kk < 8; kk++) {
            uint32_t a0 = Qs[(kk * 8 + tig    ) * QSTR + wq + g];
            uint32_t a1 = Qs[(kk * 8 + tig    ) * QSTR + wq + g + 8];
            uint32_t a2 = Qs[(kk * 8 + tig + 4) * QSTR + wq + g];
            uint32_t a3 = Qs[(kk * 8 + tig + 4) * QSTR + wq + g + 8];
            #pragma unroll
            for (int nt = 0; nt < 8; nt++) {
                uint32_t b0 = Ks[(kk * 8 + tig    ) * KSTR + nt * 8 + g];
                uint32_t b1 = Ks[(kk * 8 + tig + 4) * KSTR + nt * 8 + g];
                MMA_TF32(acc_s[nt], a0, a1, a2, a3, b0, b1);
            }
        }

        // ---- online softmax: rows wq+g (r=0) and wq+g+8 (r=1) ----
        #pragma unroll
        for (int r = 0; r < 2; r++) {
            float mx = -1e30f;
            #pragma unroll
            for (int nt = 0; nt < 8; nt++) {
                acc_s[nt][2 * r]     *= 0.125f;
                acc_s[nt][2 * r + 1] *= 0.125f;
                mx = fmaxf(mx, fmaxf(acc_s[nt][2 * r], acc_s[nt][2 * r + 1]));
            }
            mx = fmaxf(mx, __shfl_xor_sync(0xffffffffu, mx, 1));
            mx = fmaxf(mx, __shfl_xor_sync(0xffffffffu, mx, 2));
            float mnew = fmaxf(mrow[r], mx);
            float cf = __expf(mrow[r] - mnew);
            float rs = 0.f;
            int qrow = wq + g + r * 8;
            #pragma unroll
            for (int nt = 0; nt < 8; nt++) {
                float p0 = __expf(acc_s[nt][2 * r]     - mnew);
                float p1 = __expf(acc_s[nt][2 * r + 1] - mnew);
                uint2 pu = {f2tf32(p0), f2tf32(p1)};
                *(uint2*)&Ps[qrow * PSTR + nt * 8 + 2 * tig] = pu;
                rs += p0 + p1;
            }
            rs += __shfl_xor_sync(0xffffffffu, rs, 1);
            rs += __shfl_xor_sync(0xffffffffu, rs, 2);
            lrow[r] = lrow[r] * cf + rs;
            mrow[r] = mnew;
            corr[qrow] = cf;            // 4 lanes write same value
        }
        __syncthreads();

        // ---- O^T = V P^T : rescale then accumulate ----
        #pragma unroll
        for (int nt = 0; nt < 8; nt++) {
            int qc = qh + nt * 8 + 2 * tig;
            float c0 = corr[qc], c1 = corr[qc + 1];
            acc_o[nt][0] *= c0; acc_o[nt][1] *= c1;
            acc_o[nt][2] *= c0; acc_o[nt][3] *= c1;
        }
        #pragma unroll
        for (int kk = 0; kk < 8; kk++) {
            uint32_t a0 = Vs[(dt + g    ) * KSTR + kk * 8 + tig];
            uint32_t a1 = Vs[(dt + g + 8) * KSTR + kk * 8 + tig];
            uint32_t a2 = Vs[(dt + g    ) * KSTR + kk * 8 + tig + 4];
            uint32_t a3 = Vs[(dt + g + 8) * KSTR + kk * 8 + tig + 4];
            #pragma unroll
            for (int nt = 0; nt < 8; nt++) {
                uint32_t b0 = Ps[(qh + nt * 8 + g) * PSTR + kk * 8 + tig];
                uint32_t b1 = Ps[(qh + nt * 8 + g) * PSTR + kk * 8 + tig + 4];
                MMA_TF32(acc_o[nt], a0, a1, a2, a3, b0, b1);
            }
        }
    }

    // publish 1/l, then scale + store O^T[d][q] -> g_att[b][h*64+d][q0+q]
    linv[wq + g]     = 1.0f / lrow[0];
    linv[wq + g + 8] = 1.0f / lrow[1];
    __syncthreads();
    float* op = g_att + ((size_t)b * NC + h * HD) * NSP + q0;
    #pragma unroll
    for (int nt = 0; nt < 8; nt++) {
        int qc = qh + nt * 8 + 2 * tig;
        float i0 = linv[qc], i1 = linv[qc + 1];
        float2 v0 = {acc_o[nt][0] * i0, acc_o[nt][1] * i1};
        float2 v1 = {acc_o[nt][2] * i0, acc_o[nt][3] * i1};
        *(float2*)&op[(size_t)(dt + g    ) * NSP + qc] = v0;
        *(float2*)&op[(size_t)(dt + g + 8) * NSP + qc] = v1;
    }
}

// ============================================================================
extern "C" void kernel_launch(void* const* d_in, const int* in_sizes, int n_in,
                              void* d_out, int out_size) {
    const float* x      = (const float*)d_in[0];
    const float* gn_w   = (const float*)d_in[1];
    const float* gn_b   = (const float*)d_in[2];
    const float* qkv_w  = (const float*)d_in[3];
    const float* qkv_b  = (const float*)d_in[4];
    const float* proj_w = (const float*)d_in[5];
    const float* proj_b = (const float*)d_in[6];
    float* out = (float*)d_out;

    float *p_xn, *p_att, *p_qkv;
    cudaGetSymbolAddress((void**)&p_xn, g_xn);
    cudaGetSymbolAddress((void**)&p_att, g_att);
    cudaGetSymbolAddress((void**)&p_qkv, g_qkv);

    cudaFuncSetAttribute(attn_mma, cudaFuncAttributeMaxDynamicSharedMemorySize,
                         ATTN_SMEM);

    gn_kernel<<<NB * NG, 256>>>(x, gn_w, gn_b);
    gemm_mma<<<dim3(8, 12, NB), 256>>>(qkv_w, p_xn, qkv_b, nullptr, p_qkv);
    attn_mma<<<dim3(NSP / QT, NH, NB), 256, ATTN_SMEM>>>();
    gemm_mma<<<dim3(8, 4, NB), 256>>>(proj_w, p_att, proj_b, x, out);
}